// round 13
// baseline (speedup 1.0000x reference)
#include <cuda_runtime.h>
#include <cuda_fp16.h>
#include <math.h>
#include <stdint.h>

#define NN   50000
#define EE   800000
#define ET   (EE + NN)
#define HH   8
#define DHD  16
#define F1   128          // HH * DHD
#define DIN  128
#define DOUT 64
#define CHUNK 25088       // 196 * 128, node split for agg1/gemm2 pipeline

// ---------------- scratch (static device allocations; no cudaMalloc) --------
__device__ __half g_h1h[NN * F1];   // x @ W1   (fp16 messages)
__device__ __half g_h2h[NN * DOUT]; // out1 @ W2 (fp16 messages)
__device__ float g_as1[NN * HH];
__device__ float g_ad1[NN * HH];
__device__ float g_out1[NN * F1];   // layer-1 output (elu'd) = layer-2 input (fp32)
__device__ float g_as2[NN];
__device__ float g_ad2[NN];
__device__ unsigned long long g_edge[ET];  // packed (src | dst<<17 | localpos<<34)
__device__ int   g_deg[NN];
__device__ int   g_off[NN];
__device__ int   g_adj[ET];         // CSR: src lists grouped by dst
__device__ int   g_is64;
__device__ int   g_ctr;

// ---------------- helpers ---------------------------------------------------
__device__ __forceinline__ float lrelu(float x) { return x > 0.f ? x : 0.2f * x; }
__device__ __forceinline__ int clampN(int v) {
    return v < 0 ? 0 : (v >= NN ? NN - 1 : v);
}
__device__ __forceinline__ unsigned long long packE(int s, int d, int lp) {
    return (unsigned long long)(unsigned)s
         | ((unsigned long long)(unsigned)d  << 17)
         | ((unsigned long long)(unsigned)lp << 34);
}

__device__ __forceinline__ void split_tf32(float f, uint32_t& hi, uint32_t& lo) {
    uint32_t h;
    asm("cvt.rna.tf32.f32 %0, %1;" : "=r"(h) : "f"(f));
    float lf = f - __uint_as_float(h);
    uint32_t l;
    asm("cvt.rna.tf32.f32 %0, %1;" : "=r"(l) : "f"(lf));
    hi = h; lo = l;
}

__device__ __forceinline__ void mma_tf32(float* d, const uint32_t* a, const uint32_t* b) {
    asm volatile(
        "mma.sync.aligned.m16n8k8.row.col.f32.tf32.tf32.f32 "
        "{%0,%1,%2,%3}, {%4,%5,%6,%7}, {%8,%9}, {%0,%1,%2,%3};\n"
        : "+f"(d[0]), "+f"(d[1]), "+f"(d[2]), "+f"(d[3])
        : "r"(a[0]), "r"(a[1]), "r"(a[2]), "r"(a[3]), "r"(b[0]), "r"(b[1]));
}

// ---------------- edge decode + CSR build ------------------------------------
__global__ void zero_deg_k(const int* __restrict__ raw) {
    int i = blockIdx.x * blockDim.x + threadIdx.x;
    if (i < NN) g_deg[i] = 0;
    if (i == 0) {
        g_ctr = 0;
        int all0 = 1;
        for (int k = 1; k < 32; k += 2)
            if (raw[k] != 0) all0 = 0;
        g_is64 = all0;
    }
}

// decode 2 edges/thread; atomicAdd return IS each edge's local slot in its dst
// segment -> pack it so scatter needs no atomic.  (EE and ET both even, so an
// edge pair never straddles the self-loop boundary.)
__global__ void decode_k(const void* __restrict__ raw) {
    int i = blockIdx.x * blockDim.x + threadIdx.x;
    int e = i * 2;
    if (e >= ET) return;
    int s0, d0, s1, d1;
    if (e < EE) {
        if (g_is64) {
            const longlong2* qs = (const longlong2*)raw;
            const longlong2* qd = (const longlong2*)((const long long*)raw + EE);
            longlong2 sv = qs[i];
            longlong2 dv = qd[i];
            s0 = (int)sv.x; s1 = (int)sv.y;
            d0 = (int)dv.x; d1 = (int)dv.y;
        } else {
            const int2* qs = (const int2*)raw;
            const int2* qd = (const int2*)((const int*)raw + EE);
            int2 sv = qs[i];
            int2 dv = qd[i];
            s0 = sv.x; s1 = sv.y;
            d0 = dv.x; d1 = dv.y;
        }
    } else {
        s0 = d0 = e - EE;
        s1 = d1 = e + 1 - EE;
    }
    s0 = clampN(s0); d0 = clampN(d0);
    s1 = clampN(s1); d1 = clampN(d1);
    int lp0 = atomicAdd(&g_deg[d0], 1);
    int lp1 = atomicAdd(&g_deg[d1], 1);
    ulonglong2 w;
    w.x = packE(s0, d0, lp0);
    w.y = packE(s1, d1, lp1);
    *reinterpret_cast<ulonglong2*>(&g_edge[e]) = w;
}

__global__ __launch_bounds__(256) void offsets_k() {
    __shared__ int wsum[8];
    __shared__ int block_base;
    int i    = blockIdx.x * 256 + threadIdx.x;
    int lane = threadIdx.x & 31;
    int wid  = threadIdx.x >> 5;
    int d = (i < NN) ? g_deg[i] : 0;
    int v = d;
#pragma unroll
    for (int o = 1; o < 32; o <<= 1) {
        int t = __shfl_up_sync(0xffffffffu, v, o);
        if (lane >= o) v += t;
    }
    if (lane == 31) wsum[wid] = v;
    __syncthreads();
    if (wid == 0) {
        int ws = (lane < 8) ? wsum[lane] : 0;
#pragma unroll
        for (int o = 1; o < 8; o <<= 1) {
            int t = __shfl_up_sync(0xffffffffu, ws, o);
            if (lane >= o) ws += t;
        }
        if (lane < 8) wsum[lane] = ws;
        if (lane == 7) block_base = atomicAdd(&g_ctr, ws);
    }
    __syncthreads();
    int excl = block_base + (v - d) + (wid ? wsum[wid - 1] : 0);
    if (i < NN) g_off[i] = excl;
}

// atomic-free scatter, 2 edges/thread.
__global__ void scatter_k() {
    int i = blockIdx.x * blockDim.x + threadIdx.x;
    int e = i * 2;
    if (e >= ET) return;
    ulonglong2 w = *reinterpret_cast<const ulonglong2*>(&g_edge[e]);
    int s0  = (int)(w.x & 0x1FFFFu);
    int d0  = (int)((w.x >> 17) & 0x1FFFFu);
    int lp0 = (int)(w.x >> 34);
    int s1  = (int)(w.y & 0x1FFFFu);
    int d1  = (int)((w.y >> 17) & 0x1FFFFu);
    int lp1 = (int)(w.y >> 34);
    g_adj[g_off[d0] + lp0] = s0;
    g_adj[g_off[d1] + lp1] = s1;
}

// ---------------- GEMM1: split-TF32, fp16 h1 out + fused alpha1 --------------
__global__ __launch_bounds__(256) void gemm1_k(
    const float* __restrict__ A, const float* __restrict__ B,
    const float* __restrict__ a_src, const float* __restrict__ a_dst, int M)
{
    const int K = 128, Ncol = F1;
    __shared__ float As[128][36];
    __shared__ float Bs[32][72];

    int tid  = threadIdx.x;
    int warp = tid >> 5, lane = tid & 31;
    int row0 = blockIdx.y * 128;
    int col0 = blockIdx.x * 64;
    int wm = (warp >> 1) * 32;
    int wn = (warp & 1) * 32;
    int gq = lane >> 2;
    int tq = lane & 3;

    float d[2][4][4];
#pragma unroll
    for (int mt = 0; mt < 2; mt++)
#pragma unroll
        for (int nt = 0; nt < 4; nt++)
#pragma unroll
            for (int r = 0; r < 4; r++) d[mt][nt][r] = 0.f;

    for (int k0 = 0; k0 < K; k0 += 32) {
#pragma unroll
        for (int i = 0; i < 4; i++) {
            int c  = tid + 256 * i;
            int r  = c >> 3, cc = (c & 7) * 4;
            float4 v = make_float4(0.f, 0.f, 0.f, 0.f);
            if (row0 + r < M)
                v = *(const float4*)&A[(size_t)(row0 + r) * K + k0 + cc];
            *(float4*)&As[r][cc] = v;
        }
#pragma unroll
        for (int i = 0; i < 2; i++) {
            int c  = tid + 256 * i;
            int r  = c >> 4, cc = (c & 15) * 4;
            float4 v = *(const float4*)&B[(size_t)(k0 + r) * Ncol + col0 + cc];
            *(float4*)&Bs[r][cc] = v;
        }
        __syncthreads();

#pragma unroll
        for (int kk = 0; kk < 4; kk++) {
            int kb = kk * 8;
            uint32_t ah[2][4], al[2][4], bh[4][2], bl[4][2];
#pragma unroll
            for (int mt = 0; mt < 2; mt++) {
                int rb = wm + mt * 16 + gq;
                int cb = kb + tq;
                split_tf32(As[rb][cb],         ah[mt][0], al[mt][0]);
                split_tf32(As[rb + 8][cb],     ah[mt][1], al[mt][1]);
                split_tf32(As[rb][cb + 4],     ah[mt][2], al[mt][2]);
                split_tf32(As[rb + 8][cb + 4], ah[mt][3], al[mt][3]);
            }
#pragma unroll
            for (int nt = 0; nt < 4; nt++) {
                int n = wn + nt * 8 + gq;
                split_tf32(Bs[kb + tq][n],     bh[nt][0], bl[nt][0]);
                split_tf32(Bs[kb + tq + 4][n], bh[nt][1], bl[nt][1]);
            }
#pragma unroll
            for (int mt = 0; mt < 2; mt++)
#pragma unroll
                for (int nt = 0; nt < 4; nt++) {
                    mma_tf32(d[mt][nt], ah[mt], bh[nt]);
                    mma_tf32(d[mt][nt], ah[mt], bl[nt]);
                    mma_tf32(d[mt][nt], al[mt], bh[nt]);
                }
        }
        __syncthreads();
    }

    // ---- fused alpha1 ----
    float2 asv[4], adv[4];
#pragma unroll
    for (int nt = 0; nt < 4; nt++) {
        int gc = col0 + wn + nt * 8 + tq * 2;
        asv[nt] = make_float2(a_src[gc], a_src[gc + 1]);
        adv[nt] = make_float2(a_dst[gc], a_dst[gc + 1]);
    }
    int head0 = (col0 + wn) >> 4;
#pragma unroll
    for (int mt = 0; mt < 2; mt++) {
#pragma unroll
        for (int rh = 0; rh < 2; rh++) {
            float sa0 = 0.f, sa1 = 0.f, sd0 = 0.f, sd1 = 0.f;
#pragma unroll
            for (int nt = 0; nt < 4; nt++) {
                float v0 = d[mt][nt][rh * 2 + 0];
                float v1 = d[mt][nt][rh * 2 + 1];
                float pa = v0 * asv[nt].x + v1 * asv[nt].y;
                float pd = v0 * adv[nt].x + v1 * adv[nt].y;
                if (nt < 2) { sa0 += pa; sd0 += pd; }
                else        { sa1 += pa; sd1 += pd; }
            }
            sa0 += __shfl_xor_sync(0xffffffffu, sa0, 1);
            sa0 += __shfl_xor_sync(0xffffffffu, sa0, 2);
            sa1 += __shfl_xor_sync(0xffffffffu, sa1, 1);
            sa1 += __shfl_xor_sync(0xffffffffu, sa1, 2);
            sd0 += __shfl_xor_sync(0xffffffffu, sd0, 1);
            sd0 += __shfl_xor_sync(0xffffffffu, sd0, 2);
            sd1 += __shfl_xor_sync(0xffffffffu, sd1, 1);
            sd1 += __shfl_xor_sync(0xffffffffu, sd1, 2);
            int r = row0 + wm + mt * 16 + rh * 8 + gq;
            if (tq == 0 && r < M) {
                g_as1[r * HH + head0]     = sa0;
                g_as1[r * HH + head0 + 1] = sa1;
                g_ad1[r * HH + head0]     = sd0;
                g_ad1[r * HH + head0 + 1] = sd1;
            }
        }
    }

    // ---- store h1 as fp16 ----
#pragma unroll
    for (int mt = 0; mt < 2; mt++) {
        int r = row0 + wm + mt * 16 + gq;
#pragma unroll
        for (int nt = 0; nt < 4; nt++) {
            int c = col0 + wn + nt * 8 + tq * 2;
            if (r < M)
                *(__half2*)&g_h1h[(size_t)r * F1 + c] =
                    __floats2half2_rn(d[mt][nt][0], d[mt][nt][1]);
            if (r + 8 < M)
                *(__half2*)&g_h1h[(size_t)(r + 8) * F1 + c] =
                    __floats2half2_rn(d[mt][nt][2], d[mt][nt][3]);
        }
    }
}

// ---------------- GEMM2: split-TF32, fp16 h2 out + fused alpha2 --------------
// Processes rows [row_base, row_base + gridDim.y*128) clipped to M.
__global__ __launch_bounds__(256) void gemm2_k(
    const float* __restrict__ A, const float* __restrict__ B,
    const float* __restrict__ a_src, const float* __restrict__ a_dst,
    int row_base, int M)
{
    const int K = 128, Ncol = DOUT;
    __shared__ float As[128][36];
    __shared__ float Bs[32][72];
    __shared__ float rsa[128][2];
    __shared__ float rsd[128][2];

    int tid  = threadIdx.x;
    int warp = tid >> 5, lane = tid & 31;
    int row0 = row_base + blockIdx.y * 128;
    int wm = (warp >> 1) * 32;
    int wn = (warp & 1) * 32;
    int gq = lane >> 2;
    int tq = lane & 3;

    float d[2][4][4];
#pragma unroll
    for (int mt = 0; mt < 2; mt++)
#pragma unroll
        for (int nt = 0; nt < 4; nt++)
#pragma unroll
            for (int r = 0; r < 4; r++) d[mt][nt][r] = 0.f;

    for (int k0 = 0; k0 < K; k0 += 32) {
#pragma unroll
        for (int i = 0; i < 4; i++) {
            int c  = tid + 256 * i;
            int r  = c >> 3, cc = (c & 7) * 4;
            float4 v = make_float4(0.f, 0.f, 0.f, 0.f);
            if (row0 + r < M)
                v = *(const float4*)&A[(size_t)(row0 + r) * K + k0 + cc];
            *(float4*)&As[r][cc] = v;
        }
#pragma unroll
        for (int i = 0; i < 2; i++) {
            int c  = tid + 256 * i;
            int r  = c >> 4, cc = (c & 15) * 4;
            float4 v = *(const float4*)&B[(size_t)(k0 + r) * Ncol + cc];
            *(float4*)&Bs[r][cc] = v;
        }
        __syncthreads();

#pragma unroll
        for (int kk = 0; kk < 4; kk++) {
            int kb = kk * 8;
            uint32_t ah[2][4], al[2][4], bh[4][2], bl[4][2];
#pragma unroll
            for (int mt = 0; mt < 2; mt++) {
                int rb = wm + mt * 16 + gq;
                int cb = kb + tq;
                split_tf32(As[rb][cb],         ah[mt][0], al[mt][0]);
                split_tf32(As[rb + 8][cb],     ah[mt][1], al[mt][1]);
                split_tf32(As[rb][cb + 4],     ah[mt][2], al[mt][2]);
                split_tf32(As[rb + 8][cb + 4], ah[mt][3], al[mt][3]);
            }
#pragma unroll
            for (int nt = 0; nt < 4; nt++) {
                int n = wn + nt * 8 + gq;
                split_tf32(Bs[kb + tq][n],     bh[nt][0], bl[nt][0]);
                split_tf32(Bs[kb + tq + 4][n], bh[nt][1], bl[nt][1]);
            }
#pragma unroll
            for (int mt = 0; mt < 2; mt++)
#pragma unroll
                for (int nt = 0; nt < 4; nt++) {
                    mma_tf32(d[mt][nt], ah[mt], bh[nt]);
                    mma_tf32(d[mt][nt], ah[mt], bl[nt]);
                    mma_tf32(d[mt][nt], al[mt], bh[nt]);
                }
        }
        __syncthreads();
    }

    // ---- fused alpha2 ----
    float2 asv[4], adv[4];
#pragma unroll
    for (int nt = 0; nt < 4; nt++) {
        int gc = wn + nt * 8 + tq * 2;
        asv[nt] = make_float2(a_src[gc], a_src[gc + 1]);
        adv[nt] = make_float2(a_dst[gc], a_dst[gc + 1]);
    }
#pragma unroll
    for (int mt = 0; mt < 2; mt++) {
#pragma unroll
        for (int rh = 0; rh < 2; rh++) {
            float sa = 0.f, sd = 0.f;
#pragma unroll
            for (int nt = 0; nt < 4; nt++) {
                float v0 = d[mt][nt][rh * 2 + 0];
                float v1 = d[mt][nt][rh * 2 + 1];
                sa += v0 * asv[nt].x + v1 * asv[nt].y;
                sd += v0 * adv[nt].x + v1 * adv[nt].y;
            }
            sa += __shfl_xor_sync(0xffffffffu, sa, 1);
            sa += __shfl_xor_sync(0xffffffffu, sa, 2);
            sd += __shfl_xor_sync(0xffffffffu, sd, 1);
            sd += __shfl_xor_sync(0xffffffffu, sd, 2);
            int lr = wm + mt * 16 + rh * 8 + gq;
            if (tq == 0) {
                rsa[lr][warp & 1] = sa;
                rsd[lr][warp & 1] = sd;
            }
        }
    }
    __syncthreads();
    if (tid < 128) {
        int r = row0 + tid;
        if (r < M) {
            g_as2[r] = rsa[tid][0] + rsa[tid][1];
            g_ad2[r] = rsd[tid][0] + rsd[tid][1];
        }
    }

    // ---- store h2 as fp16 ----
#pragma unroll
    for (int mt = 0; mt < 2; mt++) {
        int r = row0 + wm + mt * 16 + gq;
#pragma unroll
        for (int nt = 0; nt < 4; nt++) {
            int c = wn + nt * 8 + tq * 2;
            if (r < M)
                *(__half2*)&g_h2h[(size_t)r * DOUT + c] =
                    __floats2half2_rn(d[mt][nt][0], d[mt][nt][1]);
            if (r + 8 < M)
                *(__half2*)&g_h2h[(size_t)(r + 8) * DOUT + c] =
                    __floats2half2_rn(d[mt][nt][2], d[mt][nt][3]);
        }
    }
}

// ---------------- layer-1 aggregation: single pass, fp16 gather --------------
// Processes nodes [n0, n0+count).
__global__ __launch_bounds__(256) void agg1_k(const float* __restrict__ b1,
                                              int n0, int count) {
    int gid  = blockIdx.x * blockDim.x + threadIdx.x;
    int ni   = gid >> 5;
    int lane = gid & 31;
    if (ni >= count) return;
    int n    = n0 + ni;
    int base = g_off[n];
    int deg  = g_deg[n];
    int h    = lane >> 2;
    float adh = g_ad1[n * HH + h];

    float a0 = 0.f, a1 = 0.f, a2 = 0.f, a3 = 0.f, s = 0.f;
    for (int k0 = 0; k0 < deg; k0 += 32) {
        int cnt   = min(32, deg - k0);
        int src_l = (k0 + lane < deg) ? g_adj[base + k0 + lane] : 0;
        int j = 0;
        for (; j + 8 <= cnt; j += 8) {
            int srcs[8];
#pragma unroll
            for (int u = 0; u < 8; u++) srcs[u] = __shfl_sync(0xffffffffu, src_l, j + u);
            uint2 hv[8];
            float ea[8];
#pragma unroll
            for (int u = 0; u < 8; u++)
                hv[u] = *reinterpret_cast<const uint2*>(&g_h1h[(size_t)srcs[u] * F1 + lane * 4]);
#pragma unroll
            for (int u = 0; u < 8; u++)
                ea[u] = __ldg(&g_as1[srcs[u] * HH + h]);
#pragma unroll
            for (int u = 0; u < 8; u++) {
                float ex = __expf(lrelu(ea[u] + adh));
                float2 lo = __half22float2(*reinterpret_cast<__half2*>(&hv[u].x));
                float2 hi = __half22float2(*reinterpret_cast<__half2*>(&hv[u].y));
                s  += ex;
                a0 += ex * lo.x;
                a1 += ex * lo.y;
                a2 += ex * hi.x;
                a3 += ex * hi.y;
            }
        }
        for (; j < cnt; j++) {
            int   src = __shfl_sync(0xffffffffu, src_l, j);
            float ex  = __expf(lrelu(__ldg(&g_as1[src * HH + h]) + adh));
            uint2 hv = *reinterpret_cast<const uint2*>(&g_h1h[(size_t)src * F1 + lane * 4]);
            float2 lo = __half22float2(*reinterpret_cast<__half2*>(&hv.x));
            float2 hi = __half22float2(*reinterpret_cast<__half2*>(&hv.y));
            s  += ex;
            a0 += ex * lo.x;
            a1 += ex * lo.y;
            a2 += ex * hi.x;
            a3 += ex * hi.y;
        }
    }
    float inv = 1.f / (s + 1e-16f);
    float4 bb = *reinterpret_cast<const float4*>(&b1[lane * 4]);
    float r0 = a0 * inv + bb.x;
    float r1 = a1 * inv + bb.y;
    float r2 = a2 * inv + bb.z;
    float r3 = a3 * inv + bb.w;
    r0 = r0 > 0.f ? r0 : expm1f(r0);
    r1 = r1 > 0.f ? r1 : expm1f(r1);
    r2 = r2 > 0.f ? r2 : expm1f(r2);
    r3 = r3 > 0.f ? r3 : expm1f(r3);
    *reinterpret_cast<float4*>(&g_out1[(size_t)n * F1 + lane * 4]) =
        make_float4(r0, r1, r2, r3);
}

// ---------------- layer-2 aggregation + bias + log_softmax -------------------
__global__ __launch_bounds__(256) void agg2_k(const float* __restrict__ b2,
                                              float* __restrict__ out) {
    int gid  = blockIdx.x * blockDim.x + threadIdx.x;
    int n    = gid >> 5;
    int lane = gid & 31;
    if (n >= NN) return;
    int base = g_off[n];
    int deg  = g_deg[n];
    float adn = g_ad2[n];

    float a0 = 0.f, a1 = 0.f, s = 0.f;
    for (int k0 = 0; k0 < deg; k0 += 32) {
        int cnt   = min(32, deg - k0);
        int src_l = (k0 + lane < deg) ? g_adj[base + k0 + lane] : 0;
        int j = 0;
        for (; j + 8 <= cnt; j += 8) {
            int srcs[8];
#pragma unroll
            for (int u = 0; u < 8; u++) srcs[u] = __shfl_sync(0xffffffffu, src_l, j + u);
            uint32_t hv[8];
            float ea[8];
#pragma unroll
            for (int u = 0; u < 8; u++)
                hv[u] = *reinterpret_cast<const uint32_t*>(&g_h2h[(size_t)srcs[u] * DOUT + lane * 2]);
#pragma unroll
            for (int u = 0; u < 8; u++)
                ea[u] = __ldg(&g_as2[srcs[u]]);
#pragma unroll
            for (int u = 0; u < 8; u++) {
                float ex = __expf(lrelu(ea[u] + adn));
                float2 v = __half22float2(*reinterpret_cast<__half2*>(&hv[u]));
                s  += ex;
                a0 += ex * v.x;
                a1 += ex * v.y;
            }
        }
        for (; j < cnt; j++) {
            int   src = __shfl_sync(0xffffffffu, src_l, j);
            float ex  = __expf(lrelu(__ldg(&g_as2[src]) + adn));
            uint32_t hvv = *reinterpret_cast<const uint32_t*>(&g_h2h[(size_t)src * DOUT + lane * 2]);
            float2 v = __half22float2(*reinterpret_cast<__half2*>(&hvv));
            s  += ex;
            a0 += ex * v.x;
            a1 += ex * v.y;
        }
    }
    float inv = 1.f / (s + 1e-16f);
    float v0 = a0 * inv + b2[lane * 2];
    float v1 = a1 * inv + b2[lane * 2 + 1];
    *reinterpret_cast<float2*>(&out[(size_t)n * DOUT + lane * 2]) = make_float2(v0, v1);

    float m2 = fmaxf(v0, v1);
#pragma unroll
    for (int o = 16; o; o >>= 1) m2 = fmaxf(m2, __shfl_xor_sync(0xffffffffu, m2, o));
    float se = expf(v0 - m2) + expf(v1 - m2);
#pragma unroll
    for (int o = 16; o; o >>= 1) se += __shfl_xor_sync(0xffffffffu, se, o);
    float lse = m2 + logf(se);
    *reinterpret_cast<float2*>(&out[(size_t)NN * DOUT + (size_t)n * DOUT + lane * 2]) =
        make_float2(v0 - lse, v1 - lse);
}

// ---------------- launch ----------------------------------------------------
static inline int cdiv(int a, int b) { return (a + b - 1) / b; }

extern "C" void kernel_launch(void* const* d_in, const int* in_sizes, int n_in,
                              void* d_out, int out_size)
{
    const float* x = nullptr;
    const void*  ei = nullptr;
    const float *W1 = nullptr, *W2 = nullptr;
    const float *a_src1 = nullptr, *a_dst1 = nullptr, *b1 = nullptr;
    const float *a_src2 = nullptr, *a_dst2 = nullptr, *b2 = nullptr;
    int n128 = 0, n64 = 0;
    for (int i = 0; i < n_in; i++) {
        int sz = in_sizes[i];
        const void* p = d_in[i];
        if      (sz == NN * DIN)      x  = (const float*)p;
        else if (sz == 2 * EE)        ei = p;
        else if (sz == DIN * F1)      W1 = (const float*)p;
        else if (sz == F1 * DOUT)     W2 = (const float*)p;
        else if (sz == 128) {
            if      (n128 == 0) a_src1 = (const float*)p;
            else if (n128 == 1) a_dst1 = (const float*)p;
            else                b1     = (const float*)p;
            n128++;
        } else if (sz == 64) {
            if      (n64 == 0) a_src2 = (const float*)p;
            else if (n64 == 1) a_dst2 = (const float*)p;
            else               b2     = (const float*)p;
            n64++;
        }
    }
    float* out = (float*)d_out;
    (void)out_size;

    void *p_out1;
    cudaGetSymbolAddress(&p_out1, g_out1);

    cudaStream_t s2;
    cudaEvent_t ev_fork, ev_join, ev_g1, ev_a1c1;
    cudaStreamCreateWithFlags(&s2, cudaStreamNonBlocking);
    cudaEventCreateWithFlags(&ev_fork,  cudaEventDisableTiming);
    cudaEventCreateWithFlags(&ev_join,  cudaEventDisableTiming);
    cudaEventCreateWithFlags(&ev_g1,    cudaEventDisableTiming);
    cudaEventCreateWithFlags(&ev_a1c1,  cudaEventDisableTiming);

    cudaEventRecord(ev_fork, 0);
    cudaStreamWaitEvent(s2, ev_fork, 0);

    // ---- CSR build (side stream) ----
    zero_deg_k<<<cdiv(NN, 256), 256, 0, s2>>>((const int*)ei);
    decode_k<<<cdiv(ET / 2, 256), 256, 0, s2>>>(ei);
    offsets_k<<<cdiv(NN, 256), 256, 0, s2>>>();
    scatter_k<<<cdiv(ET / 2, 256), 256, 0, s2>>>();
    cudaEventRecord(ev_join, s2);

    // ---- layer-1 GEMM (+alpha fused) on main stream ----
    {
        dim3 grid(2, cdiv(NN, 128));
        gemm1_k<<<grid, 256>>>(x, W1, a_src1, a_dst1, NN);
    }
    cudaEventRecord(ev_g1, 0);

    // ---- pipelined agg1 / gemm2 ----
    const int C0 = CHUNK;            // nodes [0, C0)
    const int C1 = NN - CHUNK;       // nodes [C0, NN)

    // side stream: agg1 chunk1 (needs gemm1 + CSR; CSR already ordered on s2)
    cudaStreamWaitEvent(s2, ev_g1, 0);
    agg1_k<<<cdiv(C1, 8), 256, 0, s2>>>(b1, C0, C1);
    cudaEventRecord(ev_a1c1, s2);

    // main stream: agg1 chunk0, then gemm2 chunk0 (overlaps agg1 chunk1)
    cudaStreamWaitEvent(0, ev_join, 0);
    agg1_k<<<cdiv(C0, 8), 256>>>(b1, 0, C0);
    {
        dim3 grid(1, C0 / 128);      // 196 tiles
        gemm2_k<<<grid, 256>>>((const float*)p_out1, W2, a_src2, a_dst2, 0, NN);
    }
    // gemm2 chunk1 after agg1 chunk1
    cudaStreamWaitEvent(0, ev_a1c1, 0);
    {
        dim3 grid(1, cdiv(C1, 128)); // 195 tiles
        gemm2_k<<<grid, 256>>>((const float*)p_out1, W2, a_src2, a_dst2, C0, NN);
    }
    agg2_k<<<cdiv(NN, 8), 256>>>(b2, out);

    cudaEventDestroy(ev_fork);
    cudaEventDestroy(ev_join);
    cudaEventDestroy(ev_g1);
    cudaEventDestroy(ev_a1c1);
    cudaStreamDestroy(s2);
}

// round 15
// speedup vs baseline: 1.0912x; 1.0912x over previous
#include <cuda_runtime.h>
#include <cuda_fp16.h>
#include <math.h>
#include <stdint.h>

#define NN   50000
#define EE   800000
#define ET   (EE + NN)
#define HH   8
#define DHD  16
#define F1   128          // HH * DHD
#define DIN  128
#define DOUT 64

// ---------------- scratch (static device allocations; no cudaMalloc) --------
__device__ __half g_h1h[NN * F1];    // x @ W1   (fp16 messages)
__device__ __half g_h2h[NN * DOUT];  // out1 @ W2 (fp16 messages)
__device__ __half g_out1h[NN * F1];  // layer-1 output (elu'd), fp16 -> gemm2 A
__device__ float g_as1[NN * HH];
__device__ float g_ad1[NN * HH];
__device__ float g_as2[NN];
__device__ float g_ad2[NN];
__device__ unsigned long long g_edge[ET];  // packed (src | dst<<17 | localpos<<34)
__device__ int   g_deg[NN];
__device__ int   g_off[NN];
__device__ int   g_adj[ET];          // CSR: src lists grouped by dst
__device__ int   g_is64;
__device__ int   g_ctr;

// ---------------- helpers ---------------------------------------------------
__device__ __forceinline__ float lrelu(float x) { return x > 0.f ? x : 0.2f * x; }
__device__ __forceinline__ int clampN(int v) {
    return v < 0 ? 0 : (v >= NN ? NN - 1 : v);
}
__device__ __forceinline__ unsigned long long packE(int s, int d, int lp) {
    return (unsigned long long)(unsigned)s
         | ((unsigned long long)(unsigned)d  << 17)
         | ((unsigned long long)(unsigned)lp << 34);
}
__device__ __forceinline__ uint32_t h2u(__half2 h) {
    return *reinterpret_cast<uint32_t*>(&h);
}

__device__ __forceinline__ void split_tf32(float f, uint32_t& hi, uint32_t& lo) {
    uint32_t h;
    asm("cvt.rna.tf32.f32 %0, %1;" : "=r"(h) : "f"(f));
    float lf = f - __uint_as_float(h);
    uint32_t l;
    asm("cvt.rna.tf32.f32 %0, %1;" : "=r"(l) : "f"(lf));
    hi = h; lo = l;
}

__device__ __forceinline__ void mma_tf32(float* d, const uint32_t* a, const uint32_t* b) {
    asm volatile(
        "mma.sync.aligned.m16n8k8.row.col.f32.tf32.tf32.f32 "
        "{%0,%1,%2,%3}, {%4,%5,%6,%7}, {%8,%9}, {%0,%1,%2,%3};\n"
        : "+f"(d[0]), "+f"(d[1]), "+f"(d[2]), "+f"(d[3])
        : "r"(a[0]), "r"(a[1]), "r"(a[2]), "r"(a[3]), "r"(b[0]), "r"(b[1]));
}

__device__ __forceinline__ void mma_f16(float* d, const uint32_t* a, const uint32_t* b) {
    asm volatile(
        "mma.sync.aligned.m16n8k16.row.col.f32.f16.f16.f32 "
        "{%0,%1,%2,%3}, {%4,%5,%6,%7}, {%8,%9}, {%0,%1,%2,%3};\n"
        : "+f"(d[0]), "+f"(d[1]), "+f"(d[2]), "+f"(d[3])
        : "r"(a[0]), "r"(a[1]), "r"(a[2]), "r"(a[3]), "r"(b[0]), "r"(b[1]));
}

// ---------------- edge decode + CSR build ------------------------------------
__global__ void zero_deg_k(const int* __restrict__ raw) {
    int i = blockIdx.x * blockDim.x + threadIdx.x;
    if (i < NN) g_deg[i] = 0;
    if (i == 0) {
        g_ctr = 0;
        int all0 = 1;
        for (int k = 1; k < 32; k += 2)
            if (raw[k] != 0) all0 = 0;
        g_is64 = all0;
    }
}

// decode 2 edges/thread; atomicAdd return IS each edge's local slot.
__global__ void decode_k(const void* __restrict__ raw) {
    int i = blockIdx.x * blockDim.x + threadIdx.x;
    int e = i * 2;
    if (e >= ET) return;
    int s0, d0, s1, d1;
    if (e < EE) {
        if (g_is64) {
            const longlong2* qs = (const longlong2*)raw;
            const longlong2* qd = (const longlong2*)((const long long*)raw + EE);
            longlong2 sv = qs[i];
            longlong2 dv = qd[i];
            s0 = (int)sv.x; s1 = (int)sv.y;
            d0 = (int)dv.x; d1 = (int)dv.y;
        } else {
            const int2* qs = (const int2*)raw;
            const int2* qd = (const int2*)((const int*)raw + EE);
            int2 sv = qs[i];
            int2 dv = qd[i];
            s0 = sv.x; s1 = sv.y;
            d0 = dv.x; d1 = dv.y;
        }
    } else {
        s0 = d0 = e - EE;
        s1 = d1 = e + 1 - EE;
    }
    s0 = clampN(s0); d0 = clampN(d0);
    s1 = clampN(s1); d1 = clampN(d1);
    int lp0 = atomicAdd(&g_deg[d0], 1);
    int lp1 = atomicAdd(&g_deg[d1], 1);
    ulonglong2 w;
    w.x = packE(s0, d0, lp0);
    w.y = packE(s1, d1, lp1);
    *reinterpret_cast<ulonglong2*>(&g_edge[e]) = w;
}

__global__ __launch_bounds__(256) void offsets_k() {
    __shared__ int wsum[8];
    __shared__ int block_base;
    int i    = blockIdx.x * 256 + threadIdx.x;
    int lane = threadIdx.x & 31;
    int wid  = threadIdx.x >> 5;
    int d = (i < NN) ? g_deg[i] : 0;
    int v = d;
#pragma unroll
    for (int o = 1; o < 32; o <<= 1) {
        int t = __shfl_up_sync(0xffffffffu, v, o);
        if (lane >= o) v += t;
    }
    if (lane == 31) wsum[wid] = v;
    __syncthreads();
    if (wid == 0) {
        int ws = (lane < 8) ? wsum[lane] : 0;
#pragma unroll
        for (int o = 1; o < 8; o <<= 1) {
            int t = __shfl_up_sync(0xffffffffu, ws, o);
            if (lane >= o) ws += t;
        }
        if (lane < 8) wsum[lane] = ws;
        if (lane == 7) block_base = atomicAdd(&g_ctr, ws);
    }
    __syncthreads();
    int excl = block_base + (v - d) + (wid ? wsum[wid - 1] : 0);
    if (i < NN) g_off[i] = excl;
}

__global__ void scatter_k() {
    int i = blockIdx.x * blockDim.x + threadIdx.x;
    int e = i * 2;
    if (e >= ET) return;
    ulonglong2 w = *reinterpret_cast<const ulonglong2*>(&g_edge[e]);
    int s0  = (int)(w.x & 0x1FFFFu);
    int d0  = (int)((w.x >> 17) & 0x1FFFFu);
    int lp0 = (int)(w.x >> 34);
    int s1  = (int)(w.y & 0x1FFFFu);
    int d1  = (int)((w.y >> 17) & 0x1FFFFu);
    int lp1 = (int)(w.y >> 34);
    g_adj[g_off[d0] + lp0] = s0;
    g_adj[g_off[d1] + lp1] = s1;
}

// ---------------- GEMM1: split-TF32, fp16 h1 out + fused alpha1 --------------
__global__ __launch_bounds__(256) void gemm1_k(
    const float* __restrict__ A, const float* __restrict__ B,
    const float* __restrict__ a_src, const float* __restrict__ a_dst, int M)
{
    const int K = 128, Ncol = F1;
    __shared__ float As[128][36];
    __shared__ float Bs[32][72];

    int tid  = threadIdx.x;
    int warp = tid >> 5, lane = tid & 31;
    int row0 = blockIdx.y * 128;
    int col0 = blockIdx.x * 64;
    int wm = (warp >> 1) * 32;
    int wn = (warp & 1) * 32;
    int gq = lane >> 2;
    int tq = lane & 3;

    float d[2][4][4];
#pragma unroll
    for (int mt = 0; mt < 2; mt++)
#pragma unroll
        for (int nt = 0; nt < 4; nt++)
#pragma unroll
            for (int r = 0; r < 4; r++) d[mt][nt][r] = 0.f;

    for (int k0 = 0; k0 < K; k0 += 32) {
#pragma unroll
        for (int i = 0; i < 4; i++) {
            int c  = tid + 256 * i;
            int r  = c >> 3, cc = (c & 7) * 4;
            float4 v = make_float4(0.f, 0.f, 0.f, 0.f);
            if (row0 + r < M)
                v = *(const float4*)&A[(size_t)(row0 + r) * K + k0 + cc];
            *(float4*)&As[r][cc] = v;
        }
#pragma unroll
        for (int i = 0; i < 2; i++) {
            int c  = tid + 256 * i;
            int r  = c >> 4, cc = (c & 15) * 4;
            float4 v = *(const float4*)&B[(size_t)(k0 + r) * Ncol + col0 + cc];
            *(float4*)&Bs[r][cc] = v;
        }
        __syncthreads();

#pragma unroll
        for (int kk = 0; kk < 4; kk++) {
            int kb = kk * 8;
            uint32_t ah[2][4], al[2][4], bh[4][2], bl[4][2];
#pragma unroll
            for (int mt = 0; mt < 2; mt++) {
                int rb = wm + mt * 16 + gq;
                int cb = kb + tq;
                split_tf32(As[rb][cb],         ah[mt][0], al[mt][0]);
                split_tf32(As[rb + 8][cb],     ah[mt][1], al[mt][1]);
                split_tf32(As[rb][cb + 4],     ah[mt][2], al[mt][2]);
                split_tf32(As[rb + 8][cb + 4], ah[mt][3], al[mt][3]);
            }
#pragma unroll
            for (int nt = 0; nt < 4; nt++) {
                int n = wn + nt * 8 + gq;
                split_tf32(Bs[kb + tq][n],     bh[nt][0], bl[nt][0]);
                split_tf32(Bs[kb + tq + 4][n], bh[nt][1], bl[nt][1]);
            }
#pragma unroll
            for (int mt = 0; mt < 2; mt++)
#pragma unroll
                for (int nt = 0; nt < 4; nt++) {
                    mma_tf32(d[mt][nt], ah[mt], bh[nt]);
                    mma_tf32(d[mt][nt], ah[mt], bl[nt]);
                    mma_tf32(d[mt][nt], al[mt], bh[nt]);
                }
        }
        __syncthreads();
    }

    // ---- fused alpha1 ----
    float2 asv[4], adv[4];
#pragma unroll
    for (int nt = 0; nt < 4; nt++) {
        int gc = col0 + wn + nt * 8 + tq * 2;
        asv[nt] = make_float2(a_src[gc], a_src[gc + 1]);
        adv[nt] = make_float2(a_dst[gc], a_dst[gc + 1]);
    }
    int head0 = (col0 + wn) >> 4;
#pragma unroll
    for (int mt = 0; mt < 2; mt++) {
#pragma unroll
        for (int rh = 0; rh < 2; rh++) {
            float sa0 = 0.f, sa1 = 0.f, sd0 = 0.f, sd1 = 0.f;
#pragma unroll
            for (int nt = 0; nt < 4; nt++) {
                float v0 = d[mt][nt][rh * 2 + 0];
                float v1 = d[mt][nt][rh * 2 + 1];
                float pa = v0 * asv[nt].x + v1 * asv[nt].y;
                float pd = v0 * adv[nt].x + v1 * adv[nt].y;
                if (nt < 2) { sa0 += pa; sd0 += pd; }
                else        { sa1 += pa; sd1 += pd; }
            }
            sa0 += __shfl_xor_sync(0xffffffffu, sa0, 1);
            sa0 += __shfl_xor_sync(0xffffffffu, sa0, 2);
            sa1 += __shfl_xor_sync(0xffffffffu, sa1, 1);
            sa1 += __shfl_xor_sync(0xffffffffu, sa1, 2);
            sd0 += __shfl_xor_sync(0xffffffffu, sd0, 1);
            sd0 += __shfl_xor_sync(0xffffffffu, sd0, 2);
            sd1 += __shfl_xor_sync(0xffffffffu, sd1, 1);
            sd1 += __shfl_xor_sync(0xffffffffu, sd1, 2);
            int r = row0 + wm + mt * 16 + rh * 8 + gq;
            if (tq == 0 && r < M) {
                g_as1[r * HH + head0]     = sa0;
                g_as1[r * HH + head0 + 1] = sa1;
                g_ad1[r * HH + head0]     = sd0;
                g_ad1[r * HH + head0 + 1] = sd1;
            }
        }
    }

    // ---- store h1 as fp16 ----
#pragma unroll
    for (int mt = 0; mt < 2; mt++) {
        int r = row0 + wm + mt * 16 + gq;
#pragma unroll
        for (int nt = 0; nt < 4; nt++) {
            int c = col0 + wn + nt * 8 + tq * 2;
            if (r < M)
                *(__half2*)&g_h1h[(size_t)r * F1 + c] =
                    __floats2half2_rn(d[mt][nt][0], d[mt][nt][1]);
            if (r + 8 < M)
                *(__half2*)&g_h1h[(size_t)(r + 8) * F1 + c] =
                    __floats2half2_rn(d[mt][nt][2], d[mt][nt][3]);
        }
    }
}

// ---------------- GEMM2: native fp16 MMA (A=out1 fp16), fused alpha2 ---------
// C[M,64] = A[M,128](fp16) @ W2[128,64](fp32->fp16).  Block 128 rows, 8 warps.
__global__ __launch_bounds__(256) void gemm2_k(
    const __half* __restrict__ A, const float* __restrict__ B,
    const float* __restrict__ a_src, const float* __restrict__ a_dst, int M)
{
    const int K = 128;
    // As_u[row][kp]: uint = halves (2*kp, 2*kp+1) of A row.  16 data + 4 pad.
    __shared__ uint32_t As_u[128][20];
    // Bs_u[n][kp]: uint = halves (k=2*kp, 2*kp+1) for column n (k-major pairs).
    __shared__ uint32_t Bs_u[64][20];
    __shared__ float rsa[128][2];
    __shared__ float rsd[128][2];

    int tid  = threadIdx.x;
    int warp = tid >> 5, lane = tid & 31;
    int row0 = blockIdx.y * 128;
    int wm = (warp >> 1) * 32;
    int wn = (warp & 1) * 32;
    int gq = lane >> 2;
    int tq = lane & 3;

    float d[2][4][4];
#pragma unroll
    for (int mt = 0; mt < 2; mt++)
#pragma unroll
        for (int nt = 0; nt < 4; nt++)
#pragma unroll
            for (int r = 0; r < 4; r++) d[mt][nt][r] = 0.f;

    for (int k0 = 0; k0 < K; k0 += 32) {
        // A chunk: 128 rows x 16 uints = 2048 uints, 8 per thread
#pragma unroll
        for (int i = 0; i < 8; i++) {
            int idx = tid + 256 * i;
            int r   = idx >> 4;
            int kp  = idx & 15;
            uint32_t v = 0;
            if (row0 + r < M)
                v = *(const uint32_t*)&A[(size_t)(row0 + r) * K + k0 + kp * 2];
            As_u[r][kp] = v;
        }
        // B chunk: 64 n x 16 kpairs = 1024 uints, 4 per thread
#pragma unroll
        for (int i = 0; i < 4; i++) {
            int idx = tid + 256 * i;
            int n   = idx >> 4;
            int kp  = idx & 15;
            float b0 = B[(size_t)(k0 + kp * 2)     * DOUT + n];
            float b1 = B[(size_t)(k0 + kp * 2 + 1) * DOUT + n];
            Bs_u[n][kp] = h2u(__floats2half2_rn(b0, b1));
        }
        __syncthreads();

        // 2 k16 steps per 32-chunk
#pragma unroll
        for (int ks = 0; ks < 2; ks++) {
            int kp0 = ks * 8;        // uint offset of this k16 step
            uint32_t a[2][4], b[4][2];
#pragma unroll
            for (int mt = 0; mt < 2; mt++) {
                int rb = wm + mt * 16 + gq;
                a[mt][0] = As_u[rb][kp0 + tq];
                a[mt][1] = As_u[rb + 8][kp0 + tq];
                a[mt][2] = As_u[rb][kp0 + 4 + tq];
                a[mt][3] = As_u[rb + 8][kp0 + 4 + tq];
            }
#pragma unroll
            for (int nt = 0; nt < 4; nt++) {
                int n = wn + nt * 8 + gq;
                b[nt][0] = Bs_u[n][kp0 + tq];
                b[nt][1] = Bs_u[n][kp0 + 4 + tq];
            }
#pragma unroll
            for (int mt = 0; mt < 2; mt++)
#pragma unroll
                for (int nt = 0; nt < 4; nt++)
                    mma_f16(d[mt][nt], a[mt], b[nt]);
        }
        __syncthreads();
    }

    // ---- fused alpha2 ----
    float2 asv[4], adv[4];
#pragma unroll
    for (int nt = 0; nt < 4; nt++) {
        int gc = wn + nt * 8 + tq * 2;
        asv[nt] = make_float2(a_src[gc], a_src[gc + 1]);
        adv[nt] = make_float2(a_dst[gc], a_dst[gc + 1]);
    }
#pragma unroll
    for (int mt = 0; mt < 2; mt++) {
#pragma unroll
        for (int rh = 0; rh < 2; rh++) {
            float sa = 0.f, sd = 0.f;
#pragma unroll
            for (int nt = 0; nt < 4; nt++) {
                float v0 = d[mt][nt][rh * 2 + 0];
                float v1 = d[mt][nt][rh * 2 + 1];
                sa += v0 * asv[nt].x + v1 * asv[nt].y;
                sd += v0 * adv[nt].x + v1 * adv[nt].y;
            }
            sa += __shfl_xor_sync(0xffffffffu, sa, 1);
            sa += __shfl_xor_sync(0xffffffffu, sa, 2);
            sd += __shfl_xor_sync(0xffffffffu, sd, 1);
            sd += __shfl_xor_sync(0xffffffffu, sd, 2);
            int lr = wm + mt * 16 + rh * 8 + gq;
            if (tq == 0) {
                rsa[lr][warp & 1] = sa;
                rsd[lr][warp & 1] = sd;
            }
        }
    }
    __syncthreads();
    if (tid < 128) {
        int r = row0 + tid;
        if (r < M) {
            g_as2[r] = rsa[tid][0] + rsa[tid][1];
            g_ad2[r] = rsd[tid][0] + rsd[tid][1];
        }
    }

    // ---- store h2 as fp16 ----
#pragma unroll
    for (int mt = 0; mt < 2; mt++) {
        int r = row0 + wm + mt * 16 + gq;
#pragma unroll
        for (int nt = 0; nt < 4; nt++) {
            int c = wn + nt * 8 + tq * 2;
            if (r < M)
                *(__half2*)&g_h2h[(size_t)r * DOUT + c] =
                    __floats2half2_rn(d[mt][nt][0], d[mt][nt][1]);
            if (r + 8 < M)
                *(__half2*)&g_h2h[(size_t)(r + 8) * DOUT + c] =
                    __floats2half2_rn(d[mt][nt][2], d[mt][nt][3]);
        }
    }
}

// ---------------- layer-1 aggregation: single pass, fp16 gather --------------
__global__ __launch_bounds__(256) void agg1_k(const float* __restrict__ b1) {
    int gid  = blockIdx.x * blockDim.x + threadIdx.x;
    int n    = gid >> 5;
    int lane = gid & 31;
    if (n >= NN) return;
    int base = g_off[n];
    int deg  = g_deg[n];
    int h    = lane >> 2;
    float adh = g_ad1[n * HH + h];

    float a0 = 0.f, a1 = 0.f, a2 = 0.f, a3 = 0.f, s = 0.f;
    for (int k0 = 0; k0 < deg; k0 += 32) {
        int cnt   = min(32, deg - k0);
        int src_l = (k0 + lane < deg) ? g_adj[base + k0 + lane] : 0;
        int j = 0;
        for (; j + 8 <= cnt; j += 8) {
            int srcs[8];
#pragma unroll
            for (int u = 0; u < 8; u++) srcs[u] = __shfl_sync(0xffffffffu, src_l, j + u);
            uint2 hv[8];
            float ea[8];
#pragma unroll
            for (int u = 0; u < 8; u++)
                hv[u] = *reinterpret_cast<const uint2*>(&g_h1h[(size_t)srcs[u] * F1 + lane * 4]);
#pragma unroll
            for (int u = 0; u < 8; u++)
                ea[u] = __ldg(&g_as1[srcs[u] * HH + h]);
#pragma unroll
            for (int u = 0; u < 8; u++) {
                float ex = __expf(lrelu(ea[u] + adh));
                float2 lo = __half22float2(*reinterpret_cast<__half2*>(&hv[u].x));
                float2 hi = __half22float2(*reinterpret_cast<__half2*>(&hv[u].y));
                s  += ex;
                a0 += ex * lo.x;
                a1 += ex * lo.y;
                a2 += ex * hi.x;
                a3 += ex * hi.y;
            }
        }
        for (; j < cnt; j++) {
            int   src = __shfl_sync(0xffffffffu, src_l, j);
            float ex  = __expf(lrelu(__ldg(&g_as1[src * HH + h]) + adh));
            uint2 hv = *reinterpret_cast<const uint2*>(&g_h1h[(size_t)src * F1 + lane * 4]);
            float2 lo = __half22float2(*reinterpret_cast<__half2*>(&hv.x));
            float2 hi = __half22float2(*reinterpret_cast<__half2*>(&hv.y));
            s  += ex;
            a0 += ex * lo.x;
            a1 += ex * lo.y;
            a2 += ex * hi.x;
            a3 += ex * hi.y;
        }
    }
    float inv = 1.f / (s + 1e-16f);
    float4 bb = *reinterpret_cast<const float4*>(&b1[lane * 4]);
    float r0 = a0 * inv + bb.x;
    float r1 = a1 * inv + bb.y;
    float r2 = a2 * inv + bb.z;
    float r3 = a3 * inv + bb.w;
    r0 = r0 > 0.f ? r0 : expm1f(r0);
    r1 = r1 > 0.f ? r1 : expm1f(r1);
    r2 = r2 > 0.f ? r2 : expm1f(r2);
    r3 = r3 > 0.f ? r3 : expm1f(r3);
    uint2 o;
    o.x = h2u(__floats2half2_rn(r0, r1));
    o.y = h2u(__floats2half2_rn(r2, r3));
    *reinterpret_cast<uint2*>(&g_out1h[(size_t)n * F1 + lane * 4]) = o;
}

// ---------------- layer-2 aggregation + bias + log_softmax -------------------
__global__ __launch_bounds__(256) void agg2_k(const float* __restrict__ b2,
                                              float* __restrict__ out) {
    int gid  = blockIdx.x * blockDim.x + threadIdx.x;
    int n    = gid >> 5;
    int lane = gid & 31;
    if (n >= NN) return;
    int base = g_off[n];
    int deg  = g_deg[n];
    float adn = g_ad2[n];

    float a0 = 0.f, a1 = 0.f, s = 0.f;
    for (int k0 = 0; k0 < deg; k0 += 32) {
        int cnt   = min(32, deg - k0);
        int src_l = (k0 + lane < deg) ? g_adj[base + k0 + lane] : 0;
        int j = 0;
        for (; j + 8 <= cnt; j += 8) {
            int srcs[8];
#pragma unroll
            for (int u = 0; u < 8; u++) srcs[u] = __shfl_sync(0xffffffffu, src_l, j + u);
            uint32_t hv[8];
            float ea[8];
#pragma unroll
            for (int u = 0; u < 8; u++)
                hv[u] = *reinterpret_cast<const uint32_t*>(&g_h2h[(size_t)srcs[u] * DOUT + lane * 2]);
#pragma unroll
            for (int u = 0; u < 8; u++)
                ea[u] = __ldg(&g_as2[srcs[u]]);
#pragma unroll
            for (int u = 0; u < 8; u++) {
                float ex = __expf(lrelu(ea[u] + adn));
                float2 v = __half22float2(*reinterpret_cast<__half2*>(&hv[u]));
                s  += ex;
                a0 += ex * v.x;
                a1 += ex * v.y;
            }
        }
        for (; j < cnt; j++) {
            int   src = __shfl_sync(0xffffffffu, src_l, j);
            float ex  = __expf(lrelu(__ldg(&g_as2[src]) + adn));
            uint32_t hvv = *reinterpret_cast<const uint32_t*>(&g_h2h[(size_t)src * DOUT + lane * 2]);
            float2 v = __half22float2(*reinterpret_cast<__half2*>(&hvv));
            s  += ex;
            a0 += ex * v.x;
            a1 += ex * v.y;
        }
    }
    float inv = 1.f / (s + 1e-16f);
    float v0 = a0 * inv + b2[lane * 2];
    float v1 = a1 * inv + b2[lane * 2 + 1];
    *reinterpret_cast<float2*>(&out[(size_t)n * DOUT + lane * 2]) = make_float2(v0, v1);

    float m2 = fmaxf(v0, v1);
#pragma unroll
    for (int o = 16; o; o >>= 1) m2 = fmaxf(m2, __shfl_xor_sync(0xffffffffu, m2, o));
    float se = expf(v0 - m2) + expf(v1 - m2);
#pragma unroll
    for (int o = 16; o; o >>= 1) se += __shfl_xor_sync(0xffffffffu, se, o);
    float lse = m2 + logf(se);
    *reinterpret_cast<float2*>(&out[(size_t)NN * DOUT + (size_t)n * DOUT + lane * 2]) =
        make_float2(v0 - lse, v1 - lse);
}

// ---------------- launch ----------------------------------------------------
static inline int cdiv(int a, int b) { return (a + b - 1) / b; }

extern "C" void kernel_launch(void* const* d_in, const int* in_sizes, int n_in,
                              void* d_out, int out_size)
{
    const float* x = nullptr;
    const void*  ei = nullptr;
    const float *W1 = nullptr, *W2 = nullptr;
    const float *a_src1 = nullptr, *a_dst1 = nullptr, *b1 = nullptr;
    const float *a_src2 = nullptr, *a_dst2 = nullptr, *b2 = nullptr;
    int n128 = 0, n64 = 0;
    for (int i = 0; i < n_in; i++) {
        int sz = in_sizes[i];
        const void* p = d_in[i];
        if      (sz == NN * DIN)      x  = (const float*)p;
        else if (sz == 2 * EE)        ei = p;
        else if (sz == DIN * F1)      W1 = (const float*)p;
        else if (sz == F1 * DOUT)     W2 = (const float*)p;
        else if (sz == 128) {
            if      (n128 == 0) a_src1 = (const float*)p;
            else if (n128 == 1) a_dst1 = (const float*)p;
            else                b1     = (const float*)p;
            n128++;
        } else if (sz == 64) {
            if      (n64 == 0) a_src2 = (const float*)p;
            else if (n64 == 1) a_dst2 = (const float*)p;
            else               b2     = (const float*)p;
            n64++;
        }
    }
    float* out = (float*)d_out;
    (void)out_size;

    void *p_out1h;
    cudaGetSymbolAddress(&p_out1h, g_out1h);

    cudaStream_t s2;
    cudaEvent_t ev_fork, ev_join;
    cudaStreamCreateWithFlags(&s2, cudaStreamNonBlocking);
    cudaEventCreateWithFlags(&ev_fork, cudaEventDisableTiming);
    cudaEventCreateWithFlags(&ev_join, cudaEventDisableTiming);

    cudaEventRecord(ev_fork, 0);
    cudaStreamWaitEvent(s2, ev_fork, 0);

    // ---- CSR build (side stream) ----
    zero_deg_k<<<cdiv(NN, 256), 256, 0, s2>>>((const int*)ei);
    decode_k<<<cdiv(ET / 2, 256), 256, 0, s2>>>(ei);
    offsets_k<<<cdiv(NN, 256), 256, 0, s2>>>();
    scatter_k<<<cdiv(ET / 2, 256), 256, 0, s2>>>();
    cudaEventRecord(ev_join, s2);

    // ---- layer-1 GEMM (+alpha fused) on main stream ----
    {
        dim3 grid(2, cdiv(NN, 128));
        gemm1_k<<<grid, 256>>>(x, W1, a_src1, a_dst1, NN);
    }

    cudaStreamWaitEvent(0, ev_join, 0);
    agg1_k<<<cdiv(NN, 8), 256>>>(b1);

    // ---- layer 2 ----
    {
        dim3 grid(1, cdiv(NN, 128));
        gemm2_k<<<grid, 256>>>((const __half*)p_out1h, W2, a_src2, a_dst2, NN);
    }
    agg2_k<<<cdiv(NN, 8), 256>>>(b2, out);

    cudaEventDestroy(ev_fork);
    cudaEventDestroy(ev_join);
    cudaStreamDestroy(s2);
}